// round 8
// baseline (speedup 1.0000x reference)
#include <cuda_runtime.h>
#include <cstdint>

// ---------------------------------------------------------------------------
// EdgeScoringMLP via bf16 tensor cores + 3-pass Dekker split (hi*hi+hi*lo+lo*hi).
//   logit(e) = W3 . relu( relu(LN(e_in @ W1 + b1)) @ W2 + b2 ) + b3
//   e_in @ W1 = Pa[i] + Pb[j] + a0*W1[256,:] + a1*W1[257,:]   (P precomputed)
// R8 (= R7 resubmit after infra failure): warpgroup N-split edge GEMM —
//     4 warps cooperate on a 64-edge tile, each warp owns 16 output columns;
//     B-fragment smem traffic drops 16x per edge. Cross-warp epilogue reduce.
// ---------------------------------------------------------------------------

#define HD 128
#define PCOL 256
#define MAXN 100000
#define PW 68              // padded row stride (u32): (4g+tig)%32 all-distinct

__device__ float g_P[(size_t)MAXN * PCOL];

// ---- bf16 helpers ---------------------------------------------------------
static __device__ __forceinline__ uint32_t pack_bf16x2(float lo, float hi) {
    uint32_t d;
    asm("cvt.rn.bf16x2.f32 %0, %1, %2;" : "=r"(d) : "f"(hi), "f"(lo));
    return d;
}
static __device__ __forceinline__ void split_pair(float x0, float x1,
                                                  uint32_t& hi, uint32_t& lo) {
    hi = pack_bf16x2(x0, x1);
    float h0 = __uint_as_float(hi << 16);
    float h1 = __uint_as_float(hi & 0xFFFF0000u);
    lo = pack_bf16x2(x0 - h0, x1 - h1);
}
static __device__ __forceinline__ void mma_bf16(
    float& c0, float& c1, float& c2, float& c3,
    uint32_t a0, uint32_t a1, uint32_t a2, uint32_t a3,
    uint32_t b0, uint32_t b1)
{
    asm volatile(
        "mma.sync.aligned.m16n8k16.row.col.f32.bf16.bf16.f32 "
        "{%0,%1,%2,%3},{%4,%5,%6,%7},{%8,%9},{%0,%1,%2,%3};"
        : "+f"(c0), "+f"(c1), "+f"(c2), "+f"(c3)
        : "r"(a0), "r"(a1), "r"(a2), "r"(a3), "r"(b0), "r"(b1));
}
static __device__ __forceinline__ void bar_wg(int id) {
    asm volatile("bar.sync %0, 128;" :: "r"(id) : "memory");
}

// ---------------------------------------------------------------------------
// Kernel 1: P = emb @ Wsel. (unchanged from R6)
// ---------------------------------------------------------------------------
__global__ void __launch_bounds__(256, 1)
precompute_kernel(const float* __restrict__ emb,
                  const float* __restrict__ W1,
                  float* __restrict__ P,
                  int N)
{
    extern __shared__ uint32_t smu[];
    uint32_t* Whi = smu;                  // [128][PW]
    uint32_t* Wlo = Whi + 128 * PW;
    uint32_t* Ahi = Wlo + 128 * PW;       // [128][PW]
    uint32_t* Alo = Ahi + 128 * PW;

    int tid  = threadIdx.x;
    int half = blockIdx.y;
    int n0g  = blockIdx.x * 128;

    for (int t = tid; t < 128 * 64; t += 256) {
        int o = t & 127, kp = t >> 7;
        float e0 = W1[(size_t)(2 * kp     + half * 128) * HD + o];
        float e1 = W1[(size_t)(2 * kp + 1 + half * 128) * HD + o];
        uint32_t hi, lo; split_pair(e0, e1, hi, lo);
        Whi[o * PW + kp] = hi; Wlo[o * PW + kp] = lo;
    }
    for (int t = tid; t < 128 * 64; t += 256) {
        int r = t >> 6, kp = t & 63;
        int node = n0g + r; if (node >= N) node = N - 1;
        float2 v = *(const float2*)(emb + (size_t)node * HD + 2 * kp);
        uint32_t hi, lo; split_pair(v.x, v.y, hi, lo);
        Ahi[r * PW + kp] = hi; Alo[r * PW + kp] = lo;
    }
    __syncthreads();

    int wid = tid >> 5, lane = tid & 31;
    int g = lane >> 2, tig = lane & 3;
    int mt = wid >> 1, nh = wid & 1;
    int m0 = mt * 32;

    float C[2][8][4];
    #pragma unroll
    for (int tt = 0; tt < 2; tt++)
        #pragma unroll
        for (int nt = 0; nt < 8; nt++)
            #pragma unroll
            for (int q = 0; q < 4; q++) C[tt][nt][q] = 0.f;

    #pragma unroll
    for (int kt = 0; kt < 8; kt++) {
        int kb = kt * 8 + tig;
        uint32_t ah[2][4], al[2][4];
        #pragma unroll
        for (int tt = 0; tt < 2; tt++) {
            int r0 = m0 + tt * 16 + g;
            ah[tt][0] = Ahi[r0       * PW + kb];
            ah[tt][1] = Ahi[(r0 + 8) * PW + kb];
            ah[tt][2] = Ahi[r0       * PW + kb + 4];
            ah[tt][3] = Ahi[(r0 + 8) * PW + kb + 4];
            al[tt][0] = Alo[r0       * PW + kb];
            al[tt][1] = Alo[(r0 + 8) * PW + kb];
            al[tt][2] = Alo[r0       * PW + kb + 4];
            al[tt][3] = Alo[(r0 + 8) * PW + kb + 4];
        }
        #pragma unroll
        for (int nt = 0; nt < 8; nt++) {
            int nc = nh * 64 + nt * 8 + g;
            uint32_t bh0 = Whi[nc * PW + kb], bh1 = Whi[nc * PW + kb + 4];
            uint32_t bl0 = Wlo[nc * PW + kb], bl1 = Wlo[nc * PW + kb + 4];
            #pragma unroll
            for (int tt = 0; tt < 2; tt++) {
                mma_bf16(C[tt][nt][0], C[tt][nt][1], C[tt][nt][2], C[tt][nt][3],
                         ah[tt][0], ah[tt][1], ah[tt][2], ah[tt][3], bh0, bh1);
                mma_bf16(C[tt][nt][0], C[tt][nt][1], C[tt][nt][2], C[tt][nt][3],
                         ah[tt][0], ah[tt][1], ah[tt][2], ah[tt][3], bl0, bl1);
                mma_bf16(C[tt][nt][0], C[tt][nt][1], C[tt][nt][2], C[tt][nt][3],
                         al[tt][0], al[tt][1], al[tt][2], al[tt][3], bh0, bh1);
            }
        }
    }

    #pragma unroll
    for (int tt = 0; tt < 2; tt++) {
        int r0 = n0g + m0 + tt * 16 + g;
        int r1 = r0 + 8;
        #pragma unroll
        for (int nt = 0; nt < 8; nt++) {
            int col = half * 128 + nh * 64 + nt * 8 + 2 * tig;
            if (r0 < N) *(float2*)(P + (size_t)r0 * PCOL + col) =
                make_float2(C[tt][nt][0], C[tt][nt][1]);
            if (r1 < N) *(float2*)(P + (size_t)r1 * PCOL + col) =
                make_float2(C[tt][nt][2], C[tt][nt][3]);
        }
    }
}

// ---------------------------------------------------------------------------
// Kernel 2: persistent fused edge pipeline. CTA 256 thr = 2 warpgroups.
// Warpgroup processes 64-edge chunks: each of its 4 warps gathers 16 edges
// (LN+ReLU+split into shared X[64]), then computes all 64 rows x its 16
// output columns (nq quarter); epilogue partial W3-dots reduced via smem.
// ---------------------------------------------------------------------------
__global__ void __launch_bounds__(256, 2)
edge_kernel(const float* __restrict__ P,
            const int* __restrict__ eidx,        // [2][E] int32
            const float* __restrict__ attr,      // [E][2]
            const float* __restrict__ W1,        // rows 256,257
            const float* __restrict__ b1,
            const float* __restrict__ lng,
            const float* __restrict__ lnb,
            const float* __restrict__ W2,        // [128][64]
            const float* __restrict__ b2,
            const float* __restrict__ W3,
            const float* __restrict__ b3,
            float* __restrict__ out,
            int E)
{
    extern __shared__ uint32_t smu[];
    uint32_t* W2hi = smu;                      // [64][PW]
    uint32_t* W2lo = W2hi + 64 * PW;
    uint32_t* Xbase = W2lo + 64 * PW;          // 2 wg x (Xhi[64][PW], Xlo[64][PW])
    float* part = (float*)(Xbase + 2 * 2 * 64 * PW);  // [2][64][4]
    float* w3s  = part + 2 * 64 * 4;           // 64
    float* b2s  = w3s + 64;                    // 64
    float* b3s  = b2s + 64;                    // 1

    int tid = threadIdx.x;

    for (int t = tid; t < 64 * 64; t += 256) {
        int kp = t >> 6, o = t & 63;
        float e0 = W2[(size_t)(2 * kp)     * 64 + o];
        float e1 = W2[(size_t)(2 * kp + 1) * 64 + o];
        uint32_t hi, lo; split_pair(e0, e1, hi, lo);
        W2hi[o * PW + kp] = hi; W2lo[o * PW + kp] = lo;
    }
    if (tid < 64) { w3s[tid] = W3[tid]; b2s[tid] = b2[tid]; }
    if (tid == 0) b3s[0] = b3[0];
    __syncthreads();

    int wid = tid >> 5, lane = tid & 31;
    int g = lane >> 2, tig = lane & 3;
    int wg = wid >> 2;          // warpgroup 0/1
    int nq = wid & 3;           // warp-in-group: gather quarter + col quarter
    uint32_t* Xhi = Xbase + wg * 2 * 64 * PW;
    uint32_t* Xlo = Xhi + 64 * PW;
    float* pw = part + wg * 64 * 4;
    int c0 = 4 * lane;
    const float inv_h = 1.0f / 128.0f;
    const float2* attr2 = (const float2*)attr;

    // hoisted per-lane LN constants
    float4 w1a_r = *(const float4*)(W1 + 256 * HD + c0);
    float4 w1b_r = *(const float4*)(W1 + 257 * HD + c0);
    float4 b1_r  = *(const float4*)(b1 + c0);
    float4 g_r   = *(const float4*)(lng + c0);
    float4 be_r  = *(const float4*)(lnb + c0);
    float  b3v   = b3s[0];

    int nchunks = (E + 63) >> 6;
    int wgidx   = blockIdx.x * 2 + wg;
    int wstride = gridDim.x * 2;

    for (int ch = wgidx; ch < nchunks; ch += wstride) {
        int e_base  = ch << 6;
        int my_base = e_base + 16 * nq;

        // lane-parallel prefetch of this warp's 16 edges
        int e_l = my_base + (lane & 15); if (e_l >= E) e_l = E - 1;
        int    i_l = eidx[e_l];
        int    j_l = eidx[(size_t)E + e_l];
        float2 a_l = attr2[e_l];

        // ---- gather + LN + ReLU + split-pack -> X rows [16nq, 16nq+16) ----
        #pragma unroll 4
        for (int ee = 0; ee < 16; ee++) {
            int   i  = __shfl_sync(0xffffffffu, i_l, ee);
            int   j  = __shfl_sync(0xffffffffu, j_l, ee);
            float ax = __shfl_sync(0xffffffffu, a_l.x, ee);
            float ay = __shfl_sync(0xffffffffu, a_l.y, ee);

            float4 pa = *(const float4*)(P + (size_t)i * PCOL + c0);
            float4 pb = *(const float4*)(P + (size_t)j * PCOL + 128 + c0);

            float h0 = pa.x + pb.x + ax * w1a_r.x + ay * w1b_r.x + b1_r.x;
            float h1 = pa.y + pb.y + ax * w1a_r.y + ay * w1b_r.y + b1_r.y;
            float h2 = pa.z + pb.z + ax * w1a_r.z + ay * w1b_r.z + b1_r.z;
            float h3 = pa.w + pb.w + ax * w1a_r.w + ay * w1b_r.w + b1_r.w;

            float s  = h0 + h1 + h2 + h3;
            float sq = h0 * h0 + h1 * h1 + h2 * h2 + h3 * h3;
            #pragma unroll
            for (int off = 16; off > 0; off >>= 1) {
                s  += __shfl_xor_sync(0xffffffffu, s,  off);
                sq += __shfl_xor_sync(0xffffffffu, sq, off);
            }
            float mean = s * inv_h;
            float var  = sq * inv_h - mean * mean;
            float rstd = rsqrtf(var + 1e-5f);

            float x0 = fmaxf((h0 - mean) * rstd * g_r.x + be_r.x, 0.f);
            float x1 = fmaxf((h1 - mean) * rstd * g_r.y + be_r.y, 0.f);
            float x2 = fmaxf((h2 - mean) * rstd * g_r.z + be_r.z, 0.f);
            float x3 = fmaxf((h3 - mean) * rstd * g_r.w + be_r.w, 0.f);

            uint32_t hA, lA, hB, lB;
            split_pair(x0, x1, hA, lA);
            split_pair(x2, x3, hB, lB);
            int row = 16 * nq + ee;
            *(uint2*)(Xhi + row * PW + 2 * lane) = make_uint2(hA, hB);
            *(uint2*)(Xlo + row * PW + 2 * lane) = make_uint2(lA, lB);
        }
        bar_wg(1 + wg);   // X[64] complete for this warpgroup

        // ---- GEMM2: C[64 rows][16 cols owned by this warp] ----
        float C[4][2][4];
        #pragma unroll
        for (int nt = 0; nt < 2; nt++) {
            float bb0 = b2s[16 * nq + 8 * nt + 2 * tig];
            float bb1 = b2s[16 * nq + 8 * nt + 2 * tig + 1];
            #pragma unroll
            for (int mt = 0; mt < 4; mt++) {
                C[mt][nt][0] = bb0; C[mt][nt][1] = bb1;
                C[mt][nt][2] = bb0; C[mt][nt][3] = bb1;
            }
        }

        #pragma unroll
        for (int kt = 0; kt < 8; kt++) {
            int kb = kt * 8 + tig;
            // B fragments for this warp's 2 col-tiles (held across mt)
            uint32_t B[2][4];
            #pragma unroll
            for (int nt = 0; nt < 2; nt++) {
                int nc = 16 * nq + 8 * nt + g;
                B[nt][0] = W2hi[nc * PW + kb];
                B[nt][1] = W2hi[nc * PW + kb + 4];
                B[nt][2] = W2lo[nc * PW + kb];
                B[nt][3] = W2lo[nc * PW + kb + 4];
            }
            #pragma unroll
            for (int mt = 0; mt < 4; mt++) {
                int r0 = 16 * mt + g;
                uint32_t ah0 = Xhi[r0       * PW + kb];
                uint32_t ah1 = Xhi[(r0 + 8) * PW + kb];
                uint32_t ah2 = Xhi[r0       * PW + kb + 4];
                uint32_t ah3 = Xhi[(r0 + 8) * PW + kb + 4];
                uint32_t al0 = Xlo[r0       * PW + kb];
                uint32_t al1 = Xlo[(r0 + 8) * PW + kb];
                uint32_t al2 = Xlo[r0       * PW + kb + 4];
                uint32_t al3 = Xlo[(r0 + 8) * PW + kb + 4];
                #pragma unroll
                for (int nt = 0; nt < 2; nt++) {
                    mma_bf16(C[mt][nt][0], C[mt][nt][1], C[mt][nt][2], C[mt][nt][3],
                             ah0, ah1, ah2, ah3, B[nt][0], B[nt][1]);
                    mma_bf16(C[mt][nt][0], C[mt][nt][1], C[mt][nt][2], C[mt][nt][3],
                             ah0, ah1, ah2, ah3, B[nt][2], B[nt][3]);
                    mma_bf16(C[mt][nt][0], C[mt][nt][1], C[mt][nt][2], C[mt][nt][3],
                             al0, al1, al2, al3, B[nt][0], B[nt][1]);
                }
            }
        }

        // ---- ReLU + partial W3 dot over this warp's 16 cols ----
        #pragma unroll
        for (int mt = 0; mt < 4; mt++) {
            float p0 = 0.f, p1 = 0.f;
            #pragma unroll
            for (int nt = 0; nt < 2; nt++) {
                float w30 = w3s[16 * nq + 8 * nt + 2 * tig];
                float w31 = w3s[16 * nq + 8 * nt + 2 * tig + 1];
                p0 += fmaxf(C[mt][nt][0], 0.f) * w30 + fmaxf(C[mt][nt][1], 0.f) * w31;
                p1 += fmaxf(C[mt][nt][2], 0.f) * w30 + fmaxf(C[mt][nt][3], 0.f) * w31;
            }
            p0 += __shfl_xor_sync(0xffffffffu, p0, 1);
            p0 += __shfl_xor_sync(0xffffffffu, p0, 2);
            p1 += __shfl_xor_sync(0xffffffffu, p1, 1);
            p1 += __shfl_xor_sync(0xffffffffu, p1, 2);
            if (tig == 0) {
                pw[(16 * mt + g)     * 4 + nq] = p0;
                pw[(16 * mt + g + 8) * 4 + nq] = p1;
            }
        }
        bar_wg(1 + wg);   // partials complete

        // ---- final reduce: warp nq writes edges [16nq, 16nq+16) ----
        if (lane < 16) {
            int el = 16 * nq + lane;
            float4 v = *(const float4*)(pw + el * 4);
            int e = e_base + el;
            if (e < E) out[e] = v.x + v.y + v.z + v.w + b3v;
        }
        // no third barrier needed: next pw write happens only after the next
        // post-gather bar, which the reader warp must reach first.
    }
}

// ---------------------------------------------------------------------------
// Launch
// ---------------------------------------------------------------------------
extern "C" void kernel_launch(void* const* d_in, const int* in_sizes, int n_in,
                              void* d_out, int out_size)
{
    const float* node_embed = (const float*)d_in[0];
    const int*   eidx       = (const int*)d_in[1];
    const float* attr       = (const float*)d_in[2];
    const float* W1         = (const float*)d_in[3];
    const float* b1         = (const float*)d_in[4];
    const float* lng        = (const float*)d_in[5];
    const float* lnb        = (const float*)d_in[6];
    const float* W2         = (const float*)d_in[7];
    const float* b2         = (const float*)d_in[8];
    const float* W3         = (const float*)d_in[9];
    const float* b3         = (const float*)d_in[10];
    float* out = (float*)d_out;

    int N = in_sizes[0] / HD;
    int E = in_sizes[2] / 2;

    float* P = nullptr;
    cudaGetSymbolAddress((void**)&P, g_P);

    const int PRE_SMEM  = 4 * 128 * PW * 4;                                   // 139264 B
    const int EDGE_SMEM = (2 * 64 * PW + 2 * 2 * 64 * PW + 2 * 64 * 4 + 129) * 4; // ~107 KB

    cudaFuncSetAttribute(precompute_kernel,
                         cudaFuncAttributeMaxDynamicSharedMemorySize, PRE_SMEM);
    cudaFuncSetAttribute(edge_kernel,
                         cudaFuncAttributeMaxDynamicSharedMemorySize, EDGE_SMEM);

    dim3 pre_grid((N + 127) / 128, 2);
    precompute_kernel<<<pre_grid, 256, PRE_SMEM>>>(node_embed, W1, P, N);

    edge_kernel<<<296, 256, EDGE_SMEM>>>(P, eidx, attr, W1, b1, lng, lnb,
                                         W2, b2, W3, b3, out, E);
}